// round 13
// baseline (speedup 1.0000x reference)
#include <cuda_runtime.h>
#include <cuda_fp16.h>
#include <cstdint>
#include <math.h>

#define NROWS 16384
#define DDIM  64
#define BM    128
#define BN    64
#define NTILES   (NROWS / BN)     // 256
#define CHUNK    16               // tiles per task
#define NCHUNKS  (NTILES / CHUNK) // 16 chunks per rowblock
#define NTASKS   ((NROWS / BM) * NCHUNKS)   // 2048
#define GRID_P   444
#define NTHR  256
#define SCALE_A 28.853900817779268f   // log2(e)/tau
#define LN2F    0.6931471805599453f
#define BIAS_H2 0xCA00CA00u           // packed half2(-12, -12)

__device__ __half g_ah[NROWS * DDIM];      // z1n * log2(e)/tau  [m][k]
__device__ __half g_bh[NROWS * DDIM];      // z2n               [n][k]
__device__ float  g_rowsum[NCHUNKS * NROWS];   // biased by 2^-12 (cancels)
__device__ float  g_pos[NROWS];                // biased logit (cancels)
__device__ float  g_part1[64];
__device__ unsigned g_task = 0;            // dynamic ticket (reset by normalize)
__device__ unsigned g_fin  = 0;            // finalize last-block counter

__device__ __forceinline__ uint32_t smem_u32(const void* p) {
    uint32_t a;
    asm("{ .reg .u64 t; cvta.to.shared.u64 t, %1; cvt.u32.u64 %0, t; }" : "=r"(a) : "l"(p));
    return a;
}
__device__ __forceinline__ uint32_t ex2_h2(uint32_t x) {
    uint32_t r; asm("ex2.approx.f16x2 %0, %1;" : "=r"(r) : "r"(x)); return r;
}
__device__ __forceinline__ uint32_t hadd2u(uint32_t a, uint32_t b) {
    uint32_t r; asm("add.rn.f16x2 %0, %1, %2;" : "=r"(r) : "r"(a), "r"(b)); return r;
}
__device__ __forceinline__ float2 h2f(uint32_t u) {
    __half2 h = *reinterpret_cast<__half2*>(&u);
    return __half22float2(h);
}
#define LDSM_X4(r0, r1, r2, r3, addr) \
    asm volatile("ldmatrix.sync.aligned.m8n8.x4.shared.b16 {%0,%1,%2,%3}, [%4];" \
        : "=r"(r0), "=r"(r1), "=r"(r2), "=r"(r3) : "r"(addr))
#define MMA16816_F16(d, a, b) \
    asm volatile("mma.sync.aligned.m16n8k16.row.col.f16.f16.f16.f16 " \
        "{%0,%1}, {%2,%3,%4,%5}, {%6,%7}, {%0,%1};" \
        : "+r"((d)[0]), "+r"((d)[1]) \
        : "r"((a)[0]), "r"((a)[1]), "r"((a)[2]), "r"((a)[3]), "r"((b)[0]), "r"((b)[1]))
#define CP_ASYNC16(dst, src) \
    asm volatile("cp.async.cg.shared.global [%0], [%1], 16;" :: "r"(dst), "l"(src))
#define CP_COMMIT()  asm volatile("cp.async.commit_group;" ::: "memory")
#define CP_WAIT(n)   asm volatile("cp.async.wait_group %0;" :: "n"(n) : "memory")

// ─────────────── Kernel 1: L2-normalize + fp16 quantize + scale fold ────────
__global__ void normalize_kernel(const float* __restrict__ z1,
                                 const float* __restrict__ z2) {
    if (blockIdx.x == 0 && threadIdx.x == 0) { g_task = 0; g_fin = 0; }

    int warp = blockIdx.x * (blockDim.x >> 5) + (threadIdx.x >> 5);
    int lane = threadIdx.x & 31;
    int row  = warp * 2 + (lane >> 4);
    int l16  = lane & 15;

    const float* src; __half* dst; float scale; int r;
    if (row < NROWS) { src = z1; dst = g_ah; r = row;          scale = SCALE_A; }
    else             { src = z2; dst = g_bh; r = row - NROWS;  scale = 1.0f;    }

    float4 v = ((const float4*)(src + (size_t)r * DDIM))[l16];
    float ss = v.x * v.x + v.y * v.y + v.z * v.z + v.w * v.w;
    #pragma unroll
    for (int off = 8; off; off >>= 1)
        ss += __shfl_xor_sync(0xffffffffu, ss, off);
    float inv = scale / fmaxf(sqrtf(ss), 1e-12f);
    __half2 h0 = __floats2half2_rn(v.x * inv, v.y * inv);
    __half2 h1 = __floats2half2_rn(v.z * inv, v.w * inv);
    uint2 o = make_uint2(*(uint32_t*)&h0, *(uint32_t*)&h1);
    ((uint2*)(dst + (size_t)r * DDIM))[l16] = o;
}

// ── Kernel 2: persistent fp16 GEMM, B fragments direct from GMEM (L1),
//    barrier-free mainloop, 3 CTAs/SM ────────────────────────────────────────
// smem: A stage [0,16K) (reduction overlay after fragment extraction)
__global__ void __launch_bounds__(NTHR, 3) gemm_lse_kernel() {
    __shared__ __align__(128) char smem[16384];
    __shared__ int s_task;
    const uint32_t sb = smem_u32(smem);
    const int tid = threadIdx.x, lane = tid & 31, w = tid >> 5;
    const int wm = w >> 1, wn = w & 1;          // 4x2 warp grid, 32x32 tiles
    const int g = lane >> 3, r8 = lane & 7;
    const int q = lane >> 2, p4 = lane & 3;

    // Per-thread B base (uint32 units): row n0 = wn*32 + lane/4, k-pair lane%4.
    // Fragment (ni, ks, h): bbase[ni*256 + ks*8 + h*4]; per tile advance 2048.
    const uint32_t* bwarp = (const uint32_t*)g_bh + (wn * 32 + q) * 32 + p4;

    for (;;) {
        if (tid == 0) s_task = (int)atomicAdd(&g_task, 1u);
        __syncthreads();
        const int task = s_task;
        if (task >= NTASKS) break;
        const int rb = task >> 4, ck = task & 15, t0 = ck << 4;

        // Stage A tile via cp.async (amortized over 16 tiles).
        {
            const uint4* asrc = (const uint4*)(g_ah + (size_t)rb * BM * DDIM);
            #pragma unroll
            for (int i = tid; i < 1024; i += NTHR) {
                int r = i >> 3, c = i & 7;
                CP_ASYNC16(sb + (uint32_t)(r * 128 + ((c ^ (r & 7)) << 4)), asrc + i);
            }
            CP_COMMIT();
        }
        CP_WAIT(0);
        __syncthreads();

        uint32_t afr[2][4][4];
        #pragma unroll
        for (int mi = 0; mi < 2; mi++)
            #pragma unroll
            for (int ks = 0; ks < 4; ks++) {
                int m  = wm * 32 + mi * 16 + (g & 1) * 8 + r8;
                int kc = ks * 2 + (g >> 1);
                uint32_t addr = sb + (uint32_t)(m * 128 + ((kc ^ (m & 7)) << 4));
                LDSM_X4(afr[mi][ks][0], afr[mi][ks][1], afr[mi][ks][2], afr[mi][ks][3], addr);
            }
        __syncthreads();                    // afr extracted; A smem reusable

        float s[4] = {0.f, 0.f, 0.f, 0.f};
        uint32_t hacc[4] = {0u, 0u, 0u, 0u};
        const uint32_t* bt = bwarp + (size_t)t0 * 2048;   // tile t0 base

        #pragma unroll 1
        for (int it = 0; it < CHUNK; it++) {
            const int t = t0 + it;

            // Accumulators pre-biased to -12: MMA yields logit-12 directly.
            uint32_t c_[2][4][2];
            #pragma unroll
            for (int mi = 0; mi < 2; mi++)
                #pragma unroll
                for (int ni = 0; ni < 4; ni++) {
                    c_[mi][ni][0] = BIAS_H2; c_[mi][ni][1] = BIAS_H2;
                }

            #pragma unroll
            for (int ks = 0; ks < 4; ks++) {
                uint32_t b[4][2];
                #pragma unroll
                for (int ni = 0; ni < 4; ni++) {
                    b[ni][0] = __ldg(bt + ni * 256 + ks * 8);
                    b[ni][1] = __ldg(bt + ni * 256 + ks * 8 + 4);
                }
                #pragma unroll
                for (int mi = 0; mi < 2; mi++)
                    #pragma unroll
                    for (int ni = 0; ni < 4; ni++)
                        MMA16816_F16(c_[mi][ni], afr[mi][ks], b[ni]);
            }
            bt += 2048;                     // next 64-row B tile

            // Diagonal capture: rows rb*128+[0,128) x cols t*64+[0,64)
            if ((t >> 1) == rb) {
                const int coff = (t & 1) << 6;
                #pragma unroll
                for (int mi = 0; mi < 2; mi++)
                    #pragma unroll
                    for (int ni = 0; ni < 4; ni++) {
                        float2 f0 = h2f(c_[mi][ni][0]);
                        float2 f1 = h2f(c_[mi][ni][1]);
                        int r0 = wm * 32 + mi * 16 + q, r1 = r0 + 8;
                        int cb = coff + wn * 32 + ni * 8 + 2 * p4;
                        if (r0 == cb)     g_pos[rb * BM + r0] = f0.x;
                        if (r0 == cb + 1) g_pos[rb * BM + r0] = f0.y;
                        if (r1 == cb)     g_pos[rb * BM + r1] = f1.x;
                        if (r1 == cb + 1) g_pos[rb * BM + r1] = f1.y;
                    }
            }

            // All-fp16 epilogue: ex2.f16x2 on raw MMA regs, HADD2 trees
            #pragma unroll
            for (int mi = 0; mi < 2; mi++)
                #pragma unroll
                for (int jj = 0; jj < 2; jj++) {
                    uint32_t e0 = ex2_h2(c_[mi][0][jj]);
                    uint32_t e1 = ex2_h2(c_[mi][1][jj]);
                    uint32_t e2 = ex2_h2(c_[mi][2][jj]);
                    uint32_t e3 = ex2_h2(c_[mi][3][jj]);
                    uint32_t tsum = hadd2u(hadd2u(e0, e1), hadd2u(e2, e3));
                    hacc[mi * 2 + jj] = hadd2u(hacc[mi * 2 + jj], tsum);
                }
            if (it & 1) {                    // drain fp16 partials every 2 tiles
                #pragma unroll
                for (int slot = 0; slot < 4; slot++) {
                    float2 f = h2f(hacc[slot]);
                    s[slot] += f.x + f.y;
                    hacc[slot] = 0u;
                }
            }
        }

        // Per-chunk row-sum reduction — overlay on A stage (dead after afr).
        float* red = (float*)smem;          // [128][8] = 4KB
        #pragma unroll
        for (int slot = 0; slot < 4; slot++) {
            int mi = slot >> 1, hi = slot & 1;
            int r = wm * 32 + mi * 16 + hi * 8 + q;
            red[r * 8 + wn * 4 + p4] = s[slot];
        }
        __syncthreads();
        if (tid < BM) {
            float tot = 0.f;
            #pragma unroll
            for (int i = 0; i < 8; i++) tot += red[tid * 8 + i];
            g_rowsum[ck * NROWS + rb * BM + tid] = tot;
        }
        // Loop-top sync (after ticket fetch) fences red/A reuse for next task.
    }
}

// ───────── Kernel 3: per-row LSE merge; last block does the final reduce ────
__global__ void finalize_kernel(float* __restrict__ out) {
    __shared__ float sh[256];
    int tid = threadIdx.x;
    int r = blockIdx.x * 256 + tid;
    float sum = 0.f;
    #pragma unroll
    for (int ck = 0; ck < NCHUNKS; ck++) sum += g_rowsum[ck * NROWS + r];
    // both sum and pos carry the 2^-12 / -12 bias -> cancels exactly
    sh[tid] = (log2f(sum) - g_pos[r]) * LN2F;
    __syncthreads();
    #pragma unroll
    for (int off = 128; off; off >>= 1) {
        if (tid < off) sh[tid] += sh[tid + off];
        __syncthreads();
    }
    int amLast = 0;
    if (tid == 0) {
        g_part1[blockIdx.x] = sh[0];
        __threadfence();
        amLast = (atomicAdd(&g_fin, 1u) == 63u);
    }
    amLast = __syncthreads_or(amLast);
    if (amLast) {
        if (tid == 0) g_fin = 0;           // reset for next graph replay
        if (tid < 64) sh[tid] = g_part1[tid];
        __syncthreads();
        if (tid == 0) {
            float tot = 0.f;
            #pragma unroll
            for (int i = 0; i < 64; i++) tot += sh[i];   // fixed order
            out[0] = tot * (1.0f / (float)NROWS);
        }
    }
}

// ────────────────────────────────────────────────────────────────────────────
extern "C" void kernel_launch(void* const* d_in, const int* in_sizes, int n_in,
                              void* d_out, int out_size) {
    const float* z1 = (const float*)d_in[0];
    const float* z2 = (const float*)d_in[1];
    float* out = (float*)d_out;

    normalize_kernel<<<2048, 256>>>(z1, z2);
    gemm_lse_kernel<<<GRID_P, NTHR>>>();
    finalize_kernel<<<64, 256>>>(out);
}

// round 14
// speedup vs baseline: 2.7225x; 2.7225x over previous
#include <cuda_runtime.h>
#include <cuda_fp16.h>
#include <cstdint>
#include <math.h>

#define NROWS 16384
#define DDIM  64
#define BM    128
#define BN    64
#define NTILES   (NROWS / BN)     // 256
#define CHUNK    16               // tiles per task
#define NPAIRS   (CHUNK / 2)      // 8
#define NCHUNKS  (NTILES / CHUNK) // 16 chunks per rowblock
#define NTASKS   ((NROWS / BM) * NCHUNKS)   // 2048
#define GRID_P   444
#define NTHR  256
#define SCALE_A 28.853900817779268f   // log2(e)/tau
#define LN2F    0.6931471805599453f
#define BIAS_H2 0xCA00CA00u           // packed half2(-12, -12)
#define SMEM_PA 32768                 // A stage region

__device__ __half g_ah[NROWS * DDIM];        // z1n * log2(e)/tau  [m][k]
__device__ __half g_bh[NROWS * DDIM];        // z2n               [n][k]
__device__ float  g_rowsum[2 * NCHUNKS * NROWS]; // per (chunk, wn) partials
__device__ float  g_pos[NROWS];              // biased logit (cancels)
__device__ float  g_part1[64];
__device__ unsigned g_task = 0;              // dynamic ticket
__device__ unsigned g_fin  = 0;              // finalize last-block counter

__device__ __forceinline__ uint32_t smem_u32(const void* p) {
    uint32_t a;
    asm("{ .reg .u64 t; cvta.to.shared.u64 t, %1; cvt.u32.u64 %0, t; }" : "=r"(a) : "l"(p));
    return a;
}
__device__ __forceinline__ uint32_t ex2_h2(uint32_t x) {
    uint32_t r; asm("ex2.approx.f16x2 %0, %1;" : "=r"(r) : "r"(x)); return r;
}
__device__ __forceinline__ uint32_t hadd2u(uint32_t a, uint32_t b) {
    uint32_t r; asm("add.rn.f16x2 %0, %1, %2;" : "=r"(r) : "r"(a), "r"(b)); return r;
}
__device__ __forceinline__ float2 h2f(uint32_t u) {
    __half2 h = *reinterpret_cast<__half2*>(&u);
    return __half22float2(h);
}
#define LDSM_X4(r0, r1, r2, r3, addr) \
    asm volatile("ldmatrix.sync.aligned.m8n8.x4.shared.b16 {%0,%1,%2,%3}, [%4];" \
        : "=r"(r0), "=r"(r1), "=r"(r2), "=r"(r3) : "r"(addr))
#define MMA16816_F16(d, a, b) \
    asm volatile("mma.sync.aligned.m16n8k16.row.col.f16.f16.f16.f16 " \
        "{%0,%1}, {%2,%3,%4,%5}, {%6,%7}, {%0,%1};" \
        : "+r"((d)[0]), "+r"((d)[1]) \
        : "r"((a)[0]), "r"((a)[1]), "r"((a)[2]), "r"((a)[3]), "r"((b)[0]), "r"((b)[1]))
#define CP_ASYNC16(dst, src) \
    asm volatile("cp.async.cg.shared.global [%0], [%1], 16;" :: "r"(dst), "l"(src))
#define CP_COMMIT()  asm volatile("cp.async.commit_group;" ::: "memory")
#define CP_WAIT(n)   asm volatile("cp.async.wait_group %0;" :: "n"(n) : "memory")

// ─────────────── Kernel 1: L2-normalize + fp16 quantize + scale fold ────────
__global__ void normalize_kernel(const float* __restrict__ z1,
                                 const float* __restrict__ z2) {
    if (blockIdx.x == 0 && threadIdx.x == 0) { g_task = 0; g_fin = 0; }

    int warp = blockIdx.x * (blockDim.x >> 5) + (threadIdx.x >> 5);
    int lane = threadIdx.x & 31;
    int row  = warp * 2 + (lane >> 4);
    int l16  = lane & 15;

    const float* src; __half* dst; float scale; int r;
    if (row < NROWS) { src = z1; dst = g_ah; r = row;          scale = SCALE_A; }
    else             { src = z2; dst = g_bh; r = row - NROWS;  scale = 1.0f;    }

    float4 v = ((const float4*)(src + (size_t)r * DDIM))[l16];
    float ss = v.x * v.x + v.y * v.y + v.z * v.z + v.w * v.w;
    #pragma unroll
    for (int off = 8; off; off >>= 1)
        ss += __shfl_xor_sync(0xffffffffu, ss, off);
    float inv = scale / fmaxf(sqrtf(ss), 1e-12f);
    __half2 h0 = __floats2half2_rn(v.x * inv, v.y * inv);
    __half2 h1 = __floats2half2_rn(v.z * inv, v.w * inv);
    uint2 o = make_uint2(*(uint32_t*)&h0, *(uint32_t*)&h1);
    ((uint2*)(dst + (size_t)r * DDIM))[l16] = o;
}

// ── Kernel 2: persistent fp16 GEMM, cross-task pipelined, 3 CTAs/SM ────────
// smem: B pair buf0 [0,16K), buf1 [16K,32K), A stage PA [32K,48K)
__global__ void __launch_bounds__(NTHR, 3) gemm_lse_kernel() {
    __shared__ __align__(128) char smem[49152];
    __shared__ volatile int s_next;
    const uint32_t sb = smem_u32(smem);
    const int tid = threadIdx.x, lane = tid & 31, w = tid >> 5;
    const int wm = w >> 1, wn = w & 1;          // 4x2 warp grid, 32x32 tiles
    const int g = lane >> 3, r8 = lane & 7;
    const int kg = g & 1;
    const int q = lane >> 2, p4 = lane & 3;

    uint32_t brow[2]; int bnlo[2];
    #pragma unroll
    for (int p = 0; p < 2; p++) {
        int n = wn * 32 + p * 16 + (g >> 1) * 8 + r8;
        brow[p] = (uint32_t)(n * 128);
        bnlo[p] = n & 7;
    }

    // First ticket + initial prefetch (A -> PA, B pair0 -> buf0)
    if (tid == 0) s_next = (int)atomicAdd(&g_task, 1u);
    __syncthreads();
    int task = s_next;
    if (task < NTASKS) {
        const int rb0 = task >> 4, tt0 = (task & 15) << 4;
        const uint4* asrc = (const uint4*)(g_ah + (size_t)rb0 * BM * DDIM);
        #pragma unroll
        for (int i = tid; i < 1024; i += NTHR) {
            int r = i >> 3, c = i & 7;
            CP_ASYNC16(sb + SMEM_PA + (uint32_t)(r * 128 + ((c ^ (r & 7)) << 4)), asrc + i);
        }
        const uint4* bs = (const uint4*)(g_bh + (size_t)tt0 * BN * DDIM);
        #pragma unroll
        for (int i = tid; i < 1024; i += NTHR) {
            int r = i >> 3, c = i & 7;
            CP_ASYNC16(sb + (uint32_t)(((r >> 6) << 13) + (r & 63) * 128
                                       + ((c ^ (r & 7)) << 4)), bs + i);
        }
        CP_COMMIT();
    }

    for (;;) {
        if (task >= NTASKS) break;
        const int rb = task >> 4, ck = task & 15, t0 = ck << 4;
        int nexttask = NTASKS;

        CP_WAIT(0);                         // A + B pair0 (prefetched last task)
        __syncthreads();

        uint32_t afr[2][4][4];
        #pragma unroll
        for (int mi = 0; mi < 2; mi++)
            #pragma unroll
            for (int ks = 0; ks < 4; ks++) {
                int m  = wm * 32 + mi * 16 + (g & 1) * 8 + r8;
                int kc = ks * 2 + (g >> 1);
                uint32_t addr = sb + SMEM_PA + (uint32_t)(m * 128 + ((kc ^ (m & 7)) << 4));
                LDSM_X4(afr[mi][ks][0], afr[mi][ks][1], afr[mi][ks][2], afr[mi][ks][3], addr);
            }
        // No sync needed: PA is next written only at pair 7, many barriers away.

        float s[4] = {0.f, 0.f, 0.f, 0.f};
        uint32_t hacc[4] = {0u, 0u, 0u, 0u};

        #pragma unroll 1
        for (int j = 0; j < NPAIRS; j++) {
            const int t = t0 + 2 * j;
            const uint32_t pbase = sb + (uint32_t)((j & 1) << 14);

            if (j == NPAIRS - 2 && tid == 0)
                s_next = (int)atomicAdd(&g_task, 1u);   // published by pair-6 barrier

            if (j < NPAIRS - 1) {
                // Prefetch next pair of this task (fenced by end-of-prev-pair sync).
                const uint32_t nbase = sb + (uint32_t)(((j + 1) & 1) << 14);
                const uint4* bs = (const uint4*)(g_bh + (size_t)(t + 2) * BN * DDIM);
                #pragma unroll
                for (int i = tid; i < 1024; i += NTHR) {
                    int r = i >> 3, c = i & 7;
                    CP_ASYNC16(nbase + (uint32_t)(((r >> 6) << 13) + (r & 63) * 128
                                                  + ((c ^ (r & 7)) << 4)), bs + i);
                }
                CP_COMMIT();
            } else {
                // Pair 7: prefetch NEXT task's A + B pair0 (PA and buf0 are dead).
                nexttask = s_next;
                if (nexttask < NTASKS) {
                    const int rbn = nexttask >> 4, ttn = (nexttask & 15) << 4;
                    const uint4* asrc = (const uint4*)(g_ah + (size_t)rbn * BM * DDIM);
                    #pragma unroll
                    for (int i = tid; i < 1024; i += NTHR) {
                        int r = i >> 3, c = i & 7;
                        CP_ASYNC16(sb + SMEM_PA + (uint32_t)(r * 128 + ((c ^ (r & 7)) << 4)),
                                   asrc + i);
                    }
                    const uint4* bs = (const uint4*)(g_bh + (size_t)ttn * BN * DDIM);
                    #pragma unroll
                    for (int i = tid; i < 1024; i += NTHR) {
                        int r = i >> 3, c = i & 7;
                        CP_ASYNC16(sb + (uint32_t)(((r >> 6) << 13) + (r & 63) * 128
                                                   + ((c ^ (r & 7)) << 4)), bs + i);
                    }
                    CP_COMMIT();
                }
            }

            // ── Two tiles, no barrier in between ──
            #pragma unroll
            for (int half = 0; half < 2; half++) {
                const int tt = t + half;
                const uint32_t bufb = pbase + (uint32_t)(half << 13);

                uint32_t c_[2][4][2];
                #pragma unroll
                for (int mi = 0; mi < 2; mi++)
                    #pragma unroll
                    for (int ni = 0; ni < 4; ni++) {
                        c_[mi][ni][0] = BIAS_H2; c_[mi][ni][1] = BIAS_H2;
                    }

                #pragma unroll
                for (int ks = 0; ks < 4; ks++) {
                    uint32_t b[4][2];
                    #pragma unroll
                    for (int p = 0; p < 2; p++) {
                        uint32_t addr = bufb + brow[p] +
                                        (uint32_t)((((ks * 2 + kg) ^ bnlo[p])) << 4);
                        LDSM_X4(b[2 * p][0], b[2 * p][1], b[2 * p + 1][0], b[2 * p + 1][1], addr);
                    }
                    #pragma unroll
                    for (int mi = 0; mi < 2; mi++)
                        #pragma unroll
                        for (int ni = 0; ni < 4; ni++)
                            MMA16816_F16(c_[mi][ni], afr[mi][ks], b[ni]);
                }

                // Diagonal capture: rows rb*128+[0,128) x cols tt*64+[0,64)
                if ((tt >> 1) == rb) {
                    const int coff = (tt & 1) << 6;
                    #pragma unroll
                    for (int mi = 0; mi < 2; mi++)
                        #pragma unroll
                        for (int ni = 0; ni < 4; ni++) {
                            float2 f0 = h2f(c_[mi][ni][0]);
                            float2 f1 = h2f(c_[mi][ni][1]);
                            int r0 = wm * 32 + mi * 16 + q, r1 = r0 + 8;
                            int cb = coff + wn * 32 + ni * 8 + 2 * p4;
                            if (r0 == cb)     g_pos[rb * BM + r0] = f0.x;
                            if (r0 == cb + 1) g_pos[rb * BM + r0] = f0.y;
                            if (r1 == cb)     g_pos[rb * BM + r1] = f1.x;
                            if (r1 == cb + 1) g_pos[rb * BM + r1] = f1.y;
                        }
                }

                // All-fp16 epilogue: ex2.f16x2 on raw MMA regs, HADD2 trees
                #pragma unroll
                for (int mi = 0; mi < 2; mi++)
                    #pragma unroll
                    for (int jj = 0; jj < 2; jj++) {
                        uint32_t e0 = ex2_h2(c_[mi][0][jj]);
                        uint32_t e1 = ex2_h2(c_[mi][1][jj]);
                        uint32_t e2 = ex2_h2(c_[mi][2][jj]);
                        uint32_t e3 = ex2_h2(c_[mi][3][jj]);
                        uint32_t tsum = hadd2u(hadd2u(e0, e1), hadd2u(e2, e3));
                        hacc[mi * 2 + jj] = hadd2u(hacc[mi * 2 + jj], tsum);
                    }
            }

            // Drain fp16 partials once per pair
            #pragma unroll
            for (int slot = 0; slot < 4; slot++) {
                float2 f = h2f(hacc[slot]);
                s[slot] += f.x + f.y;
                hacc[slot] = 0u;
            }

            if (j < NPAIRS - 1) {
                CP_WAIT(0);                 // next pair resident
                __syncthreads();            // + all warps done reading pbase
            }
        }

        // Row reduction via shuffles (lanes p4 0..3 share a row); no smem.
        #pragma unroll
        for (int slot = 0; slot < 4; slot++) {
            s[slot] += __shfl_xor_sync(0xffffffffu, s[slot], 1);
            s[slot] += __shfl_xor_sync(0xffffffffu, s[slot], 2);
        }
        if (p4 == 0) {
            float* dst = g_rowsum + (size_t)(ck * 2 + wn) * NROWS + rb * BM;
            #pragma unroll
            for (int slot = 0; slot < 4; slot++) {
                int mi = slot >> 1, hi = slot & 1;
                dst[wm * 32 + mi * 16 + hi * 8 + q] = s[slot];
            }
        }
        task = nexttask;
    }
}

// ───────── Kernel 3: per-row LSE merge; last block does the final reduce ────
__global__ void finalize_kernel(float* __restrict__ out) {
    __shared__ float sh[256];
    int tid = threadIdx.x;
    int r = blockIdx.x * 256 + tid;
    float sum = 0.f;
    #pragma unroll
    for (int ck = 0; ck < 2 * NCHUNKS; ck++) sum += g_rowsum[(size_t)ck * NROWS + r];
    // both sum and pos carry the 2^-12 / -12 bias -> cancels exactly
    sh[tid] = (log2f(sum) - g_pos[r]) * LN2F;
    __syncthreads();
    #pragma unroll
    for (int off = 128; off; off >>= 1) {
        if (tid < off) sh[tid] += sh[tid + off];
        __syncthreads();
    }
    int amLast = 0;
    if (tid == 0) {
        g_part1[blockIdx.x] = sh[0];
        __threadfence();
        amLast = (atomicAdd(&g_fin, 1u) == 63u);
    }
    amLast = __syncthreads_or(amLast);
    if (amLast) {
        if (tid == 0) g_fin = 0;           // reset for next graph replay
        if (tid < 64) sh[tid] = g_part1[tid];
        __syncthreads();
        if (tid == 0) {
            float tot = 0.f;
            #pragma unroll
            for (int i = 0; i < 64; i++) tot += sh[i];   // fixed order
            out[0] = tot * (1.0f / (float)NROWS);
        }
    }
}

// ────────────────────────────────────────────────────────────────────────────
extern "C" void kernel_launch(void* const* d_in, const int* in_sizes, int n_in,
                              void* d_out, int out_size) {
    const float* z1 = (const float*)d_in[0];
    const float* z2 = (const float*)d_in[1];
    float* out = (float*)d_out;

    normalize_kernel<<<2048, 256>>>(z1, z2);
    gemm_lse_kernel<<<GRID_P, NTHR>>>();
    finalize_kernel<<<64, 256>>>(out);
}

// round 15
// speedup vs baseline: 2.7927x; 1.0258x over previous
#include <cuda_runtime.h>
#include <cuda_fp16.h>
#include <cstdint>
#include <math.h>

#define NROWS 16384
#define DDIM  64
#define BM    128
#define BN    64
#define NTILES   (NROWS / BN)     // 256
#define CHUNK    16               // tiles per task
#define NPAIRS   (CHUNK / 2)      // 8
#define NCHUNKS  (NTILES / CHUNK) // 16 chunks per rowblock
#define NTASKS   ((NROWS / BM) * NCHUNKS)   // 2048
#define GRID_P   444              // 148 SMs x 3 CTAs -> all co-resident
#define NTHR  256
#define SCALE_A 28.853900817779268f   // log2(e)/tau
#define LN2F    0.6931471805599453f
#define BIAS_H2 0xCA00CA00u           // packed half2(-12, -12)
#define SMEM_A  32768                 // A stage / reduction overlay

__device__ __half g_ah[NROWS * DDIM];      // z1n * log2(e)/tau  [m][k]
__device__ __half g_bh[NROWS * DDIM];      // z2n               [n][k]
__device__ float  g_rowsum[NCHUNKS * NROWS];   // biased by 2^-12 (cancels)
__device__ float  g_pos[NROWS];                // biased logit (cancels)
__device__ float  g_part1[64];
__device__ unsigned g_task = 0;            // dynamic ticket
__device__ unsigned g_bar  = 0;            // normalize-phase grid barrier
__device__ unsigned g_done = 0;            // end-of-kernel reset counter
__device__ unsigned g_fin  = 0;            // finalize last-block counter

__device__ __forceinline__ uint32_t smem_u32(const void* p) {
    uint32_t a;
    asm("{ .reg .u64 t; cvta.to.shared.u64 t, %1; cvt.u32.u64 %0, t; }" : "=r"(a) : "l"(p));
    return a;
}
__device__ __forceinline__ uint32_t ex2_h2(uint32_t x) {
    uint32_t r; asm("ex2.approx.f16x2 %0, %1;" : "=r"(r) : "r"(x)); return r;
}
__device__ __forceinline__ uint32_t hadd2u(uint32_t a, uint32_t b) {
    uint32_t r; asm("add.rn.f16x2 %0, %1, %2;" : "=r"(r) : "r"(a), "r"(b)); return r;
}
__device__ __forceinline__ float2 h2f(uint32_t u) {
    __half2 h = *reinterpret_cast<__half2*>(&u);
    return __half22float2(h);
}
#define LDSM_X4(r0, r1, r2, r3, addr) \
    asm volatile("ldmatrix.sync.aligned.m8n8.x4.shared.b16 {%0,%1,%2,%3}, [%4];" \
        : "=r"(r0), "=r"(r1), "=r"(r2), "=r"(r3) : "r"(addr))
#define MMA16816_F16(d, a, b) \
    asm volatile("mma.sync.aligned.m16n8k16.row.col.f16.f16.f16.f16 " \
        "{%0,%1}, {%2,%3,%4,%5}, {%6,%7}, {%0,%1};" \
        : "+r"((d)[0]), "+r"((d)[1]) \
        : "r"((a)[0]), "r"((a)[1]), "r"((a)[2]), "r"((a)[3]), "r"((b)[0]), "r"((b)[1]))
#define CP_ASYNC16(dst, src) \
    asm volatile("cp.async.cg.shared.global [%0], [%1], 16;" :: "r"(dst), "l"(src))
#define CP_COMMIT()  asm volatile("cp.async.commit_group;" ::: "memory")
#define CP_WAIT(n)   asm volatile("cp.async.wait_group %0;" :: "n"(n) : "memory")

// ── Kernel 1: fused normalize phase + persistent fp16 GEMM, 3 CTAs/SM ──────
// smem: B pair0 [0,16K), B pair1 [16K,32K), A stage [32K,48K)
__global__ void __launch_bounds__(NTHR, 3) gemm_lse_kernel(
        const float* __restrict__ z1, const float* __restrict__ z2) {
    __shared__ __align__(128) char smem[49152];
    __shared__ int s_task;
    const uint32_t sb = smem_u32(smem);
    const int tid = threadIdx.x, lane = tid & 31, w = tid >> 5;
    const int wm = w >> 1, wn = w & 1;          // 4x2 warp grid, 32x32 tiles
    const int g = lane >> 3, r8 = lane & 7;
    const int kg = g & 1;
    const int q = lane >> 2, p4 = lane & 3;

    // ── Phase 1: L2-normalize + fp16 quantize + scale fold (grid-strided) ──
    {
        const int l16 = lane & 15;
        for (int wr = blockIdx.x * 8 + w; wr < NROWS; wr += GRID_P * 8) {
            int row = wr * 2 + (lane >> 4);     // covers [0, 2*NROWS)
            const float* src; __half* dst; float scale; int r;
            if (row < NROWS) { src = z1; dst = g_ah; r = row;          scale = SCALE_A; }
            else             { src = z2; dst = g_bh; r = row - NROWS;  scale = 1.0f;    }
            float4 v = ((const float4*)(src + (size_t)r * DDIM))[l16];
            float ss = v.x * v.x + v.y * v.y + v.z * v.z + v.w * v.w;
            #pragma unroll
            for (int off = 8; off; off >>= 1)
                ss += __shfl_xor_sync(0xffffffffu, ss, off);
            float inv = scale / fmaxf(sqrtf(ss), 1e-12f);
            __half2 h0 = __floats2half2_rn(v.x * inv, v.y * inv);
            __half2 h1 = __floats2half2_rn(v.z * inv, v.w * inv);
            uint2 o = make_uint2(*(uint32_t*)&h0, *(uint32_t*)&h1);
            ((uint2*)(dst + (size_t)r * DDIM))[l16] = o;
        }
        __threadfence();
        __syncthreads();
        if (tid == 0) {
            atomicAdd(&g_bar, 1u);
            unsigned v;
            do {
                asm volatile("ld.global.cg.u32 %0, [%1];" : "=r"(v) : "l"(&g_bar));
            } while (v < GRID_P);
        }
        __syncthreads();                    // all CTAs see fully-written g_ah/g_bh
    }

    // ── Phase 2: persistent GEMM + fused LSE (round-12 body) ──
    uint32_t brow[2]; int bnlo[2];
    #pragma unroll
    for (int p = 0; p < 2; p++) {
        int n = wn * 32 + p * 16 + (g >> 1) * 8 + r8;
        brow[p] = (uint32_t)(n * 128);
        bnlo[p] = n & 7;
    }

    for (;;) {
        if (tid == 0) s_task = (int)atomicAdd(&g_task, 1u);
        __syncthreads();
        const int task = s_task;
        if (task >= NTASKS) break;
        const int rb = task >> 4, ck = task & 15, t0 = ck << 4;

        // Preamble: A + B pair0 (tiles t0, t0+1), one group, wait once.
        {
            const uint4* asrc = (const uint4*)(g_ah + (size_t)rb * BM * DDIM);
            #pragma unroll
            for (int i = tid; i < 1024; i += NTHR) {
                int r = i >> 3, c = i & 7;
                CP_ASYNC16(sb + SMEM_A + (uint32_t)(r * 128 + ((c ^ (r & 7)) << 4)),
                           asrc + i);
            }
            const uint4* bs = (const uint4*)(g_bh + (size_t)t0 * BN * DDIM);
            #pragma unroll
            for (int i = tid; i < 1024; i += NTHR) {    // 2 tiles = 1024 uint4
                int r = i >> 3, c = i & 7;
                CP_ASYNC16(sb + (uint32_t)(((r >> 6) << 13) + (r & 63) * 128
                                           + ((c ^ (r & 7)) << 4)), bs + i);
            }
            CP_COMMIT();
        }
        CP_WAIT(0);
        __syncthreads();

        uint32_t afr[2][4][4];
        #pragma unroll
        for (int mi = 0; mi < 2; mi++)
            #pragma unroll
            for (int ks = 0; ks < 4; ks++) {
                int m  = wm * 32 + mi * 16 + (g & 1) * 8 + r8;
                int kc = ks * 2 + (g >> 1);
                uint32_t addr = sb + SMEM_A + (uint32_t)(m * 128 + ((kc ^ (m & 7)) << 4));
                LDSM_X4(afr[mi][ks][0], afr[mi][ks][1], afr[mi][ks][2], afr[mi][ks][3], addr);
            }

        float s[4] = {0.f, 0.f, 0.f, 0.f};
        uint32_t hacc[4] = {0u, 0u, 0u, 0u};

        #pragma unroll 1
        for (int j = 0; j < NPAIRS; j++) {
            const int t = t0 + 2 * j;
            const uint32_t pbase = sb + (uint32_t)((j & 1) << 14);
            // Prefetch next pair into the other pair-buffer (fenced by the
            // sync that ended iteration j-1).
            if (j < NPAIRS - 1) {
                const uint32_t nbase = sb + (uint32_t)(((j + 1) & 1) << 14);
                const uint4* bs = (const uint4*)(g_bh + (size_t)(t + 2) * BN * DDIM);
                #pragma unroll
                for (int i = tid; i < 1024; i += NTHR) {
                    int r = i >> 3, c = i & 7;
                    CP_ASYNC16(nbase + (uint32_t)(((r >> 6) << 13) + (r & 63) * 128
                                                  + ((c ^ (r & 7)) << 4)), bs + i);
                }
                CP_COMMIT();
            }

            // ── Two tiles, no barrier in between ──
            #pragma unroll
            for (int half = 0; half < 2; half++) {
                const int tt = t + half;
                const uint32_t bufb = pbase + (uint32_t)(half << 13);

                uint32_t c_[2][4][2];
                #pragma unroll
                for (int mi = 0; mi < 2; mi++)
                    #pragma unroll
                    for (int ni = 0; ni < 4; ni++) {
                        c_[mi][ni][0] = BIAS_H2; c_[mi][ni][1] = BIAS_H2;
                    }

                #pragma unroll
                for (int ks = 0; ks < 4; ks++) {
                    uint32_t b[4][2];
                    #pragma unroll
                    for (int p = 0; p < 2; p++) {
                        uint32_t addr = bufb + brow[p] +
                                        (uint32_t)((((ks * 2 + kg) ^ bnlo[p])) << 4);
                        LDSM_X4(b[2 * p][0], b[2 * p][1], b[2 * p + 1][0], b[2 * p + 1][1], addr);
                    }
                    #pragma unroll
                    for (int mi = 0; mi < 2; mi++)
                        #pragma unroll
                        for (int ni = 0; ni < 4; ni++)
                            MMA16816_F16(c_[mi][ni], afr[mi][ks], b[ni]);
                }

                // Diagonal capture: rows rb*128+[0,128) x cols tt*64+[0,64)
                if ((tt >> 1) == rb) {
                    const int coff = (tt & 1) << 6;
                    #pragma unroll
                    for (int mi = 0; mi < 2; mi++)
                        #pragma unroll
                        for (int ni = 0; ni < 4; ni++) {
                            float2 f0 = h2f(c_[mi][ni][0]);
                            float2 f1 = h2f(c_[mi][ni][1]);
                            int r0 = wm * 32 + mi * 16 + q, r1 = r0 + 8;
                            int cb = coff + wn * 32 + ni * 8 + 2 * p4;
                            if (r0 == cb)     g_pos[rb * BM + r0] = f0.x;
                            if (r0 == cb + 1) g_pos[rb * BM + r0] = f0.y;
                            if (r1 == cb)     g_pos[rb * BM + r1] = f1.x;
                            if (r1 == cb + 1) g_pos[rb * BM + r1] = f1.y;
                        }
                }

                // All-fp16 epilogue: ex2.f16x2 on raw MMA regs, HADD2 trees
                #pragma unroll
                for (int mi = 0; mi < 2; mi++)
                    #pragma unroll
                    for (int jj = 0; jj < 2; jj++) {
                        uint32_t e0 = ex2_h2(c_[mi][0][jj]);
                        uint32_t e1 = ex2_h2(c_[mi][1][jj]);
                        uint32_t e2 = ex2_h2(c_[mi][2][jj]);
                        uint32_t e3 = ex2_h2(c_[mi][3][jj]);
                        uint32_t tsum = hadd2u(hadd2u(e0, e1), hadd2u(e2, e3));
                        hacc[mi * 2 + jj] = hadd2u(hacc[mi * 2 + jj], tsum);
                    }
            }

            // Drain fp16 partials once per pair
            #pragma unroll
            for (int slot = 0; slot < 4; slot++) {
                float2 f = h2f(hacc[slot]);
                s[slot] += f.x + f.y;
                hacc[slot] = 0u;
            }

            if (j < NPAIRS - 1) {
                CP_WAIT(0);                 // next pair resident
                __syncthreads();            // + all warps done reading pbase
            }
        }

        // Per-chunk row-sum reduction — overlay on A stage (dead after afr).
        __syncthreads();                    // all warps done with last pair
        float* red = (float*)(smem + SMEM_A);   // [128][8]
        #pragma unroll
        for (int slot = 0; slot < 4; slot++) {
            int mi = slot >> 1, hi = slot & 1;
            int r = wm * 32 + mi * 16 + hi * 8 + q;
            red[r * 8 + wn * 4 + p4] = s[slot];
        }
        __syncthreads();
        if (tid < BM) {
            float tot = 0.f;
            #pragma unroll
            for (int i = 0; i < 8; i++) tot += red[tid * 8 + i];
            g_rowsum[ck * NROWS + rb * BM + tid] = tot;
        }
        // Loop-top sync (after ticket fetch) fences red/A reuse for next task.
    }

    // Last CTA to finish resets all counters for the next graph replay.
    if (tid == 0) {
        unsigned old = atomicAdd(&g_done, 1u);
        if (old == GRID_P - 1) {
            g_bar = 0; g_done = 0; g_task = 0;
            __threadfence();
        }
    }
}

// ───────── Kernel 2: per-row LSE merge; last block does the final reduce ────
__global__ void finalize_kernel(float* __restrict__ out) {
    __shared__ float sh[256];
    int tid = threadIdx.x;
    int r = blockIdx.x * 256 + tid;
    float sum = 0.f;
    #pragma unroll
    for (int ck = 0; ck < NCHUNKS; ck++) sum += g_rowsum[ck * NROWS + r];
    // both sum and pos carry the 2^-12 / -12 bias -> cancels exactly
    sh[tid] = (log2f(sum) - g_pos[r]) * LN2F;
    __syncthreads();
    #pragma unroll
    for (int off = 128; off; off >>= 1) {
        if (tid < off) sh[tid] += sh[tid + off];
        __syncthreads();
    }
    int amLast = 0;
    if (tid == 0) {
        g_part1[blockIdx.x] = sh[0];
        __threadfence();
        amLast = (atomicAdd(&g_fin, 1u) == 63u);
    }
    amLast = __syncthreads_or(amLast);
    if (amLast) {
        if (tid == 0) g_fin = 0;           // reset for next graph replay
        if (tid < 64) sh[tid] = g_part1[tid];
        __syncthreads();
        if (tid == 0) {
            float tot = 0.f;
            #pragma unroll
            for (int i = 0; i < 64; i++) tot += sh[i];   // fixed order
            out[0] = tot * (1.0f / (float)NROWS);
        }
    }
}

// ────────────────────────────────────────────────────────────────────────────
extern "C" void kernel_launch(void* const* d_in, const int* in_sizes, int n_in,
                              void* d_out, int out_size) {
    const float* z1 = (const float*)d_in[0];
    const float* z2 = (const float*)d_in[1];
    float* out = (float*)d_out;

    gemm_lse_kernel<<<GRID_P, NTHR>>>(z1, z2);
    finalize_kernel<<<64, 256>>>(out);
}

// round 17
// speedup vs baseline: 2.8562x; 1.0228x over previous
#include <cuda_runtime.h>
#include <cuda_fp16.h>
#include <cstdint>
#include <math.h>

#define NROWS 16384
#define DDIM  64
#define BM    128
#define BN    64
#define NTILES   (NROWS / BN)     // 256
#define CHUNK    16               // tiles per task
#define NPAIRS   (CHUNK / 2)      // 8
#define NCHUNKS  (NTILES / CHUNK) // 16 chunks per rowblock
#define NTASKS   ((NROWS / BM) * NCHUNKS)   // 2048
#define GRID_P   444
#define NTHR  256
#define SCALE_A 28.853900817779268f   // log2(e)/tau
#define LN2F    0.6931471805599453f
#define BIAS_H2 0xCA00CA00u           // packed half2(-12, -12)
#define SMEM_A  32768                 // A stage / reduction overlay

__device__ __half g_ah[NROWS * DDIM];      // z1n * log2(e)/tau  [m][k]
__device__ __half g_bh[NROWS * DDIM];      // z2n               [n][k]
__device__ float  g_rowsum[NCHUNKS * NROWS];   // biased by 2^-12 (cancels)
__device__ float  g_pos[NROWS];                // biased logit (cancels)
__device__ float  g_part1[64];
__device__ unsigned g_task = 0;            // dynamic ticket (reset by normalize)
__device__ unsigned g_fin  = 0;            // finalize last-block counter

__device__ __forceinline__ uint32_t smem_u32(const void* p) {
    uint32_t a;
    asm("{ .reg .u64 t; cvta.to.shared.u64 t, %1; cvt.u32.u64 %0, t; }" : "=r"(a) : "l"(p));
    return a;
}
__device__ __forceinline__ uint32_t ex2_h2(uint32_t x) {
    uint32_t r; asm("ex2.approx.f16x2 %0, %1;" : "=r"(r) : "r"(x)); return r;
}
__device__ __forceinline__ uint32_t hadd2u(uint32_t a, uint32_t b) {
    uint32_t r; asm("add.rn.f16x2 %0, %1, %2;" : "=r"(r) : "r"(a), "r"(b)); return r;
}
__device__ __forceinline__ float2 h2f(uint32_t u) {
    __half2 h = *reinterpret_cast<__half2*>(&u);
    return __half22float2(h);
}
#define LDSM_X4(r0, r1, r2, r3, addr) \
    asm volatile("ldmatrix.sync.aligned.m8n8.x4.shared.b16 {%0,%1,%2,%3}, [%4];" \
        : "=r"(r0), "=r"(r1), "=r"(r2), "=r"(r3) : "r"(addr))
#define MMA16816_F16(d, a, b) \
    asm volatile("mma.sync.aligned.m16n8k16.row.col.f16.f16.f16.f16 " \
        "{%0,%1}, {%2,%3,%4,%5}, {%6,%7}, {%0,%1};" \
        : "+r"((d)[0]), "+r"((d)[1]) \
        : "r"((a)[0]), "r"((a)[1]), "r"((a)[2]), "r"((a)[3]), "r"((b)[0]), "r"((b)[1]))
#define CP_ASYNC16(dst, src) \
    asm volatile("cp.async.cg.shared.global [%0], [%1], 16;" :: "r"(dst), "l"(src))
#define CP_COMMIT()  asm volatile("cp.async.commit_group;" ::: "memory")
#define CP_WAIT(n)   asm volatile("cp.async.wait_group %0;" :: "n"(n) : "memory")

// ── Kernel 1: L2-normalize + fp16 quantize + scale fold ────────────────────
// 8 lanes per row, 4 rows/warp, 2 independent float4 loads per thread (ILP 2).
__global__ void normalize_kernel(const float* __restrict__ z1,
                                 const float* __restrict__ z2) {
    if (blockIdx.x == 0 && threadIdx.x == 0) g_task = 0;   // reset ticket

    int warp = blockIdx.x * (blockDim.x >> 5) + (threadIdx.x >> 5);
    int lane = threadIdx.x & 31;
    int sub  = lane >> 3, l8 = lane & 7;
    int row  = warp * 4 + sub;                 // [0, 2*NROWS)

    const float* src; __half* dst; float scale; int r;
    if (row < NROWS) { src = z1; dst = g_ah; r = row;          scale = SCALE_A; }
    else             { src = z2; dst = g_bh; r = row - NROWS;  scale = 1.0f;    }

    const float4* s4 = (const float4*)(src + (size_t)r * DDIM);
    float4 v0 = s4[l8];
    float4 v1 = s4[l8 + 8];
    float ss = (v0.x * v0.x + v0.y * v0.y + v0.z * v0.z + v0.w * v0.w)
             + (v1.x * v1.x + v1.y * v1.y + v1.z * v1.z + v1.w * v1.w);
    #pragma unroll
    for (int off = 4; off; off >>= 1)
        ss += __shfl_xor_sync(0xffffffffu, ss, off);   // within 8-lane group
    float inv = scale / fmaxf(sqrtf(ss), 1e-12f);
    __half2 h0 = __floats2half2_rn(v0.x * inv, v0.y * inv);
    __half2 h1 = __floats2half2_rn(v0.z * inv, v0.w * inv);
    __half2 h2 = __floats2half2_rn(v1.x * inv, v1.y * inv);
    __half2 h3 = __floats2half2_rn(v1.z * inv, v1.w * inv);
    uint2* d2 = (uint2*)(dst + (size_t)r * DDIM);
    d2[l8]     = make_uint2(*(uint32_t*)&h0, *(uint32_t*)&h1);
    d2[l8 + 8] = make_uint2(*(uint32_t*)&h2, *(uint32_t*)&h3);
}

// ── Kernel 2: persistent fp16 GEMM, 2 tiles per barrier, 3 CTAs/SM ─────────
// smem: B pair0 [0,16K), B pair1 [16K,32K), A stage [32K,48K)
__global__ void __launch_bounds__(NTHR, 3) gemm_lse_kernel() {
    __shared__ __align__(128) char smem[49152];
    __shared__ int s_task;
    const uint32_t sb = smem_u32(smem);
    const int tid = threadIdx.x, lane = tid & 31, w = tid >> 5;
    const int wm = w >> 1, wn = w & 1;          // 4x2 warp grid, 32x32 tiles
    const int g = lane >> 3, r8 = lane & 7;
    const int kg = g & 1;
    const int q = lane >> 2, p4 = lane & 3;

    uint32_t brow[2]; int bnlo[2];
    #pragma unroll
    for (int p = 0; p < 2; p++) {
        int n = wn * 32 + p * 16 + (g >> 1) * 8 + r8;
        brow[p] = (uint32_t)(n * 128);
        bnlo[p] = n & 7;
    }

    for (;;) {
        if (tid == 0) s_task = (int)atomicAdd(&g_task, 1u);
        __syncthreads();
        const int task = s_task;
        if (task >= NTASKS) break;
        const int rb = task >> 4, ck = task & 15, t0 = ck << 4;

        // Preamble: A + B pair0 (tiles t0, t0+1), one group, wait once.
        {
            const uint4* asrc = (const uint4*)(g_ah + (size_t)rb * BM * DDIM);
            #pragma unroll
            for (int i = tid; i < 1024; i += NTHR) {
                int r = i >> 3, c = i & 7;
                CP_ASYNC16(sb + SMEM_A + (uint32_t)(r * 128 + ((c ^ (r & 7)) << 4)),
                           asrc + i);
            }
            const uint4* bs = (const uint4*)(g_bh + (size_t)t0 * BN * DDIM);
            #pragma unroll
            for (int i = tid; i < 1024; i += NTHR) {    // 2 tiles = 1024 uint4
                int r = i >> 3, c = i & 7;
                CP_ASYNC16(sb + (uint32_t)(((r >> 6) << 13) + (r & 63) * 128
                                           + ((c ^ (r & 7)) << 4)), bs + i);
            }
            CP_COMMIT();
        }
        CP_WAIT(0);
        __syncthreads();

        uint32_t afr[2][4][4];
        #pragma unroll
        for (int mi = 0; mi < 2; mi++)
            #pragma unroll
            for (int ks = 0; ks < 4; ks++) {
                int m  = wm * 32 + mi * 16 + (g & 1) * 8 + r8;
                int kc = ks * 2 + (g >> 1);
                uint32_t addr = sb + SMEM_A + (uint32_t)(m * 128 + ((kc ^ (m & 7)) << 4));
                LDSM_X4(afr[mi][ks][0], afr[mi][ks][1], afr[mi][ks][2], afr[mi][ks][3], addr);
            }

        float s[4] = {0.f, 0.f, 0.f, 0.f};
        uint32_t hacc[4] = {0u, 0u, 0u, 0u};

        #pragma unroll 1
        for (int j = 0; j < NPAIRS; j++) {
            const int t = t0 + 2 * j;
            const uint32_t pbase = sb + (uint32_t)((j & 1) << 14);
            // Prefetch next pair into the other pair-buffer (fenced by the
            // sync that ended iteration j-1).
            if (j < NPAIRS - 1) {
                const uint32_t nbase = sb + (uint32_t)(((j + 1) & 1) << 14);
                const uint4* bs = (const uint4*)(g_bh + (size_t)(t + 2) * BN * DDIM);
                #pragma unroll
                for (int i = tid; i < 1024; i += NTHR) {
                    int r = i >> 3, c = i & 7;
                    CP_ASYNC16(nbase + (uint32_t)(((r >> 6) << 13) + (r & 63) * 128
                                                  + ((c ^ (r & 7)) << 4)), bs + i);
                }
                CP_COMMIT();
            }

            // ── Two tiles, no barrier in between ──
            #pragma unroll
            for (int half = 0; half < 2; half++) {
                const int tt = t + half;
                const uint32_t bufb = pbase + (uint32_t)(half << 13);

                uint32_t c_[2][4][2];
                #pragma unroll
                for (int mi = 0; mi < 2; mi++)
                    #pragma unroll
                    for (int ni = 0; ni < 4; ni++) {
                        c_[mi][ni][0] = BIAS_H2; c_[mi][ni][1] = BIAS_H2;
                    }

                #pragma unroll
                for (int ks = 0; ks < 4; ks++) {
                    uint32_t b[4][2];
                    #pragma unroll
                    for (int p = 0; p < 2; p++) {
                        uint32_t addr = bufb + brow[p] +
                                        (uint32_t)((((ks * 2 + kg) ^ bnlo[p])) << 4);
                        LDSM_X4(b[2 * p][0], b[2 * p][1], b[2 * p + 1][0], b[2 * p + 1][1], addr);
                    }
                    #pragma unroll
                    for (int mi = 0; mi < 2; mi++)
                        #pragma unroll
                        for (int ni = 0; ni < 4; ni++)
                            MMA16816_F16(c_[mi][ni], afr[mi][ks], b[ni]);
                }

                // Diagonal capture: rows rb*128+[0,128) x cols tt*64+[0,64)
                if ((tt >> 1) == rb) {
                    const int coff = (tt & 1) << 6;
                    #pragma unroll
                    for (int mi = 0; mi < 2; mi++)
                        #pragma unroll
                        for (int ni = 0; ni < 4; ni++) {
                            float2 f0 = h2f(c_[mi][ni][0]);
                            float2 f1 = h2f(c_[mi][ni][1]);
                            int r0 = wm * 32 + mi * 16 + q, r1 = r0 + 8;
                            int cb = coff + wn * 32 + ni * 8 + 2 * p4;
                            if (r0 == cb)     g_pos[rb * BM + r0] = f0.x;
                            if (r0 == cb + 1) g_pos[rb * BM + r0] = f0.y;
                            if (r1 == cb)     g_pos[rb * BM + r1] = f1.x;
                            if (r1 == cb + 1) g_pos[rb * BM + r1] = f1.y;
                        }
                }

                // All-fp16 epilogue: ex2.f16x2 on raw MMA regs, HADD2 trees
                #pragma unroll
                for (int mi = 0; mi < 2; mi++)
                    #pragma unroll
                    for (int jj = 0; jj < 2; jj++) {
                        uint32_t e0 = ex2_h2(c_[mi][0][jj]);
                        uint32_t e1 = ex2_h2(c_[mi][1][jj]);
                        uint32_t e2 = ex2_h2(c_[mi][2][jj]);
                        uint32_t e3 = ex2_h2(c_[mi][3][jj]);
                        uint32_t tsum = hadd2u(hadd2u(e0, e1), hadd2u(e2, e3));
                        hacc[mi * 2 + jj] = hadd2u(hacc[mi * 2 + jj], tsum);
                    }
            }

            // Drain fp16 partials once per pair
            #pragma unroll
            for (int slot = 0; slot < 4; slot++) {
                float2 f = h2f(hacc[slot]);
                s[slot] += f.x + f.y;
                hacc[slot] = 0u;
            }

            if (j < NPAIRS - 1) {
                CP_WAIT(0);                 // next pair resident
                __syncthreads();            // + all warps done reading pbase
            }
        }

        // Per-chunk row-sum reduction — overlay on A stage (dead after afr).
        __syncthreads();                    // all warps done with last pair
        float* red = (float*)(smem + SMEM_A);   // [128][8]
        #pragma unroll
        for (int slot = 0; slot < 4; slot++) {
            int mi = slot >> 1, hi = slot & 1;
            int r = wm * 32 + mi * 16 + hi * 8 + q;
            red[r * 8 + wn * 4 + p4] = s[slot];
        }
        __syncthreads();
        if (tid < BM) {
            float tot = 0.f;
            #pragma unroll
            for (int i = 0; i < 8; i++) tot += red[tid * 8 + i];
            g_rowsum[ck * NROWS + rb * BM + tid] = tot;
        }
        // Loop-top sync (after ticket fetch) fences red/A reuse for next task.
    }
}

// ───────── Kernel 3: per-row LSE merge; last block does the final reduce ────
__global__ void finalize_kernel(float* __restrict__ out) {
    __shared__ float sh[256];
    int tid = threadIdx.x;
    int r = blockIdx.x * 256 + tid;
    float sum = 0.f;
    #pragma unroll
    for (int ck = 0; ck < NCHUNKS; ck++) sum += g_rowsum[ck * NROWS + r];
    // both sum and pos carry the 2^-12 / -12 bias -> cancels exactly
    sh[tid] = (log2f(sum) - g_pos[r]) * LN2F;
    __syncthreads();
    #pragma unroll
    for (int off = 128; off; off >>= 1) {
        if (tid < off) sh[tid] += sh[tid + off];
        __syncthreads();
    }
    int amLast = 0;
    if (tid == 0) {
        g_part1[blockIdx.x] = sh[0];
        __threadfence();
        amLast = (atomicAdd(&g_fin, 1u) == 63u);
    }
    amLast = __syncthreads_or(amLast);
    if (amLast) {
        if (tid == 0) g_fin = 0;           // reset for next graph replay
        if (tid < 64) sh[tid] = g_part1[tid];
        __syncthreads();
        if (tid == 0) {
            float tot = 0.f;
            #pragma unroll
            for (int i = 0; i < 64; i++) tot += sh[i];   // fixed order
            out[0] = tot * (1.0f / (float)NROWS);
        }
    }
}

// ────────────────────────────────────────────────────────────────────────────
extern "C" void kernel_launch(void* const* d_in, const int* in_sizes, int n_in,
                              void* d_out, int out_size) {
    const float* z1 = (const float*)d_in[0];
    const float* z2 = (const float*)d_in[1];
    float* out = (float*)d_out;

    normalize_kernel<<<1024, 256>>>(z1, z2);   // 4 rows/warp, 8 warps/block
    gemm_lse_kernel<<<GRID_P, NTHR>>>();
    finalize_kernel<<<64, 256>>>(out);
}